// round 2
// baseline (speedup 1.0000x reference)
#include <cuda_runtime.h>
#include <cstdint>

#define N_NODES 50000
#define N_EDGES 800000
#define IN_F    256
#define HEADS   4
#define OUTF    64
#define HF      256   // HEADS*OUTF
#define SLOPE   0.2f

// ---------------- scratch (device globals; no allocation allowed) ----------
__device__ __align__(16) float g_h[N_NODES * HF];        // 51.2 MB projected features
__device__ __align__(16) float g_asrc[N_NODES * HEADS];  // per-node att halves
__device__ __align__(16) float g_adst[N_NODES * HEADS];
__device__ __align__(16) float g_denom[N_NODES * HEADS]; // softmax denominators
__device__ __align__(16) float g_exself[N_NODES * HEADS];// self-loop numerators
__device__ __align__(16) float g_ex[N_EDGES * HEADS];    // per-edge numerators (12.8 MB)

__device__ __forceinline__ float leaky(float v) {
    return v > 0.0f ? v : SLOPE * v;
}

__device__ __forceinline__ void red_add_v4(float* p, float a, float b, float c, float d) {
    asm volatile("red.global.add.v4.f32 [%0], {%1,%2,%3,%4};"
                 :: "l"(p), "f"(a), "f"(b), "f"(c), "f"(d) : "memory");
}

// ---------------------------------------------------------------------------
// K1: h = x @ W   (BM=128, BN=64 == one head, BK=32; 256 threads, 8x4 microtile)
//     Epilogue fuses a_src/a_dst (per-head dot + 16-lane shfl reduction).
// ---------------------------------------------------------------------------
#define BM 128
#define BN 64
#define BK 32
#define TM 8
#define TN 4

__global__ __launch_bounds__(256) void k_gemm(const float* __restrict__ x,
                                              const float* __restrict__ W,
                                              const float* __restrict__ att_s,
                                              const float* __restrict__ att_d)
{
    __shared__ float As[BK][BM + 1];   // transposed: As[k][m]
    __shared__ float Bs[BK][BN];

    const int head = blockIdx.y;
    const int r0 = blockIdx.x * BM;
    const int c0 = head * OUTF;
    const int tid = threadIdx.x;
    const int tx = tid & 15;      // 16 cols of threads (covers BN/TN)
    const int ty = tid >> 4;      // 16 rows of threads (covers BM/TM)

    float acc[TM][TN];
#pragma unroll
    for (int i = 0; i < TM; i++)
#pragma unroll
        for (int j = 0; j < TN; j++) acc[i][j] = 0.0f;

    for (int k0 = 0; k0 < IN_F; k0 += BK) {
        // load A tile: 128x32 floats = 1024 float4, 4 per thread (transpose into As)
#pragma unroll
        for (int i = 0; i < 4; i++) {
            int q = tid + i * 256;          // float4 index
            int row = q >> 3;               // 0..127
            int cc = (q & 7) << 2;          // 0..28
            int r = r0 + row;
            float4 v = make_float4(0.f, 0.f, 0.f, 0.f);
            if (r < N_NODES) v = *(const float4*)&x[r * IN_F + k0 + cc];
            As[cc + 0][row] = v.x;
            As[cc + 1][row] = v.y;
            As[cc + 2][row] = v.z;
            As[cc + 3][row] = v.w;
        }
        // load B tile: 32x64 floats = 512 float4, 2 per thread
#pragma unroll
        for (int i = 0; i < 2; i++) {
            int q = tid + i * 256;
            int row = q >> 4;               // 0..31
            int cc = (q & 15) << 2;         // 0..60
            *(float4*)&Bs[row][cc] = *(const float4*)&W[(k0 + row) * HF + c0 + cc];
        }
        __syncthreads();

#pragma unroll
        for (int k = 0; k < BK; k++) {
            float a[TM];
#pragma unroll
            for (int i = 0; i < TM; i++) a[i] = As[k][ty * TM + i];
            float4 b = *(float4*)&Bs[k][tx * TN];
#pragma unroll
            for (int i = 0; i < TM; i++) {
                acc[i][0] = fmaf(a[i], b.x, acc[i][0]);
                acc[i][1] = fmaf(a[i], b.y, acc[i][1]);
                acc[i][2] = fmaf(a[i], b.z, acc[i][2]);
                acc[i][3] = fmaf(a[i], b.w, acc[i][3]);
            }
        }
        __syncthreads();
    }

    // epilogue: store h + fused a_src/a_dst per-head dot
    float av[TN], dv[TN];
#pragma unroll
    for (int j = 0; j < TN; j++) {
        av[j] = att_s[c0 + tx * TN + j];
        dv[j] = att_d[c0 + tx * TN + j];
    }

#pragma unroll
    for (int i = 0; i < TM; i++) {
        int m = r0 + ty * TM + i;
        bool ok = (m < N_NODES);
        if (ok) {
            float4 hv = make_float4(acc[i][0], acc[i][1], acc[i][2], acc[i][3]);
            *(float4*)&g_h[m * HF + c0 + tx * TN] = hv;
        }
        float ps = 0.f, pd = 0.f;
#pragma unroll
        for (int j = 0; j < TN; j++) {
            ps = fmaf(acc[i][j], av[j], ps);
            pd = fmaf(acc[i][j], dv[j], pd);
        }
        // reduce over 16 tx lanes (xor-closed group inside the warp)
#pragma unroll
        for (int o = 8; o > 0; o >>= 1) {
            ps += __shfl_xor_sync(0xffffffffu, ps, o);
            pd += __shfl_xor_sync(0xffffffffu, pd, o);
        }
        if (tx == 0 && ok) {
            g_asrc[m * HEADS + head] = ps;
            g_adst[m * HEADS + head] = pd;
        }
    }
}

// ---------------------------------------------------------------------------
// K2: per (node,head): self-loop numerator, init denominator
// ---------------------------------------------------------------------------
__global__ void k_node_init()
{
    int i = blockIdx.x * blockDim.x + threadIdx.x;
    if (i >= N_NODES * HEADS) return;
    float e = leaky(g_asrc[i] + g_adst[i]);
    float ex = expf(e);
    g_exself[i] = ex;
    g_denom[i] = ex;
}

// ---------------------------------------------------------------------------
// K3: per edge: numerators, accumulate denominators (edge_index is INT32)
// ---------------------------------------------------------------------------
__global__ void k_edge_exp(const int* __restrict__ ei)
{
    int e = blockIdx.x * blockDim.x + threadIdx.x;
    if (e >= N_EDGES) return;
    int s = ei[e];
    int d = ei[N_EDGES + e];
    float4 as = *(const float4*)&g_asrc[s * HEADS];
    float4 ad = *(const float4*)&g_adst[d * HEADS];
    float4 ex;
    ex.x = expf(leaky(as.x + ad.x));
    ex.y = expf(leaky(as.y + ad.y));
    ex.z = expf(leaky(as.z + ad.z));
    ex.w = expf(leaky(as.w + ad.w));
    *(float4*)&g_ex[e * HEADS] = ex;
    atomicAdd(&g_denom[d * HEADS + 0], ex.x);
    atomicAdd(&g_denom[d * HEADS + 1], ex.y);
    atomicAdd(&g_denom[d * HEADS + 2], ex.z);
    atomicAdd(&g_denom[d * HEADS + 3], ex.w);
}

// ---------------------------------------------------------------------------
// K4: init output with self-loop message + bias (fully overwrites d_out)
// ---------------------------------------------------------------------------
__global__ void k_out_init(float* __restrict__ out, const float* __restrict__ bias)
{
    int t = blockIdx.x * blockDim.x + threadIdx.x;   // float4 index
    if (t >= N_NODES * (HF / 4)) return;
    int node = t >> 6;
    int c4 = t & 63;              // float4 column
    int head = c4 >> 4;
    float alpha = g_exself[node * HEADS + head] / g_denom[node * HEADS + head];
    float4 h = *(const float4*)&g_h[node * HF + c4 * 4];
    float4 b = *(const float4*)&bias[c4 * 4];
    float4 o;
    o.x = fmaf(h.x, alpha, b.x);
    o.y = fmaf(h.y, alpha, b.y);
    o.z = fmaf(h.z, alpha, b.z);
    o.w = fmaf(h.w, alpha, b.w);
    ((float4*)out)[t] = o;
}

// ---------------------------------------------------------------------------
// K5: aggregation. one warp per edge; 256 floats = 2 float4 per lane.
//     vector reductions (red.global.add.v4.f32), no return trip.
// ---------------------------------------------------------------------------
__global__ __launch_bounds__(256) void k_agg(const int* __restrict__ ei,
                                             float* __restrict__ out)
{
    int w = (blockIdx.x * blockDim.x + threadIdx.x) >> 5;
    if (w >= N_EDGES) return;
    int lane = threadIdx.x & 31;
    int s = ei[w];
    int d = ei[N_EDGES + w];

    int h0 = lane >> 4;           // head for cols [lane*4, lane*4+3]  (0 or 1)
    int h1 = h0 + 2;              // head for cols 128 + lane*4

    float al0 = g_ex[w * HEADS + h0] / g_denom[d * HEADS + h0];
    float al1 = g_ex[w * HEADS + h1] / g_denom[d * HEADS + h1];

    const float4* hs = (const float4*)&g_h[s * HF];
    float* ob = out + d * HF;

    float4 v0 = hs[lane];
    float4 v1 = hs[32 + lane];

    red_add_v4(&ob[lane * 4],       v0.x * al0, v0.y * al0, v0.z * al0, v0.w * al0);
    red_add_v4(&ob[128 + lane * 4], v1.x * al1, v1.y * al1, v1.z * al1, v1.w * al1);
}

// ---------------------------------------------------------------------------
extern "C" void kernel_launch(void* const* d_in, const int* in_sizes, int n_in,
                              void* d_out, int out_size)
{
    const float* x     = (const float*)d_in[0];
    const int*   ei    = (const int*)d_in[1];     // int32! (JAX x64 disabled)
    const float* W     = (const float*)d_in[2];
    const float* att_s = (const float*)d_in[3];
    const float* att_d = (const float*)d_in[4];
    const float* bias  = (const float*)d_in[5];
    float*       out   = (float*)d_out;

    // K1: projection + fused attention halves
    dim3 g1((N_NODES + BM - 1) / BM, HEADS);
    k_gemm<<<g1, 256>>>(x, W, att_s, att_d);

    // K2: self-loop numerators / denom init
    k_node_init<<<(N_NODES * HEADS + 255) / 256, 256>>>();

    // K3: edge numerators + denom accumulation
    k_edge_exp<<<(N_EDGES + 255) / 256, 256>>>(ei);

    // K4: output init (self-loop message + bias)
    k_out_init<<<(N_NODES * (HF / 4) + 255) / 256, 256>>>(out, bias);

    // K5: weighted aggregation (warp per edge)
    k_agg<<<(N_EDGES * 32 + 255) / 256, 256>>>(ei, out);
}